// round 15
// baseline (speedup 1.0000x reference)
#include <cuda_runtime.h>
#include <cuda_bf16.h>
#include <cuda_fp16.h>
#include <cstdint>

#define NN 50000
#define EE 800000
#define HH 4
#define INF_ 128

// ---------------- scratch ---------------------------------------------------
__device__ uint32_t g_fh [NN * 64];   // feature as fp16x2 (64 words/row)
__device__ uint32_t g_qv [NN * 128];  // interleaved q/v fp16x2: per lane l,
                                      // words 4l..4l+3 = {q2l, q2l+1, v2l, v2l+1}
__device__ float    g_k  [NN * 128];  // k fp32 (read once per node)
__device__ uint32_t g_fth[NN * 64];   // ft as fp16x2
__device__ uint32_t g_wh [4 * 8192];  // weights fp16x2 (q,k,v,weff)
__device__ int      g_cnt[NN];
__device__ int      g_off[NN + 1];
__device__ int      g_cur[NN];
__device__ int      g_esrc[EE];

// ---------------- helpers ----------------------------------------------------
__device__ __forceinline__ uint32_t smem_u32(const void* p) {
    uint32_t a;
    asm("{ .reg .u64 t; cvta.to.shared.u64 t, %1; cvt.u32.u64 %0, t; }" : "=r"(a) : "l"(p));
    return a;
}
__device__ __forceinline__ uint2 pack4h(float4 x) {
    __half2 h0 = __float22half2_rn(make_float2(x.x, x.y));
    __half2 h1 = __float22half2_rn(make_float2(x.z, x.w));
    uint2 r;
    r.x = *reinterpret_cast<uint32_t*>(&h0);
    r.y = *reinterpret_cast<uint32_t*>(&h1);
    return r;
}
__device__ __forceinline__ void mma16816h(float* d, uint32_t a0, uint32_t a1,
                                          uint32_t a2, uint32_t a3,
                                          uint32_t b0, uint32_t b1) {
    asm volatile(
        "mma.sync.aligned.m16n8k16.row.col.f32.f16.f16.f32 "
        "{%0,%1,%2,%3}, {%4,%5,%6,%7}, {%8,%9}, {%0,%1,%2,%3};"
        : "+f"(d[0]), "+f"(d[1]), "+f"(d[2]), "+f"(d[3])
        : "r"(a0), "r"(a1), "r"(a2), "r"(a3), "r"(b0), "r"(b1));
}
#define LM4(r, a) asm volatile( \
    "ldmatrix.sync.aligned.m8n8.x4.shared.b16 {%0,%1,%2,%3}, [%4];" \
    : "=r"((r)[0]), "=r"((r)[1]), "=r"((r)[2]), "=r"((r)[3]) : "r"(a))

// ---------------- conversion kernels ----------------------------------------
__global__ void conv_feat_k(const float* __restrict__ F) {
    int idx = blockIdx.x * blockDim.x + threadIdx.x;
    if (idx < NN * 32)
        ((uint2*)g_fh)[idx] = pack4h(((const float4*)F)[idx]);
}
__global__ void conv_w_k(const float* __restrict__ Wq, const float* __restrict__ Wk,
                         const float* __restrict__ Wv, const float* __restrict__ Ws) {
    int idx = blockIdx.x * blockDim.x + threadIdx.x;
    if (idx >= 4 * 4096) return;
    int w = idx >> 12, off = idx & 4095;
    float4 x;
    if (w == 0)      x = ((const float4*)Wq)[off];
    else if (w == 1) x = ((const float4*)Wk)[off];
    else if (w == 2) x = ((const float4*)Wv)[off];
    else {
        const float4* s = (const float4*)Ws;
        float4 a = s[off], b = s[off + 4096], c = s[off + 8192], d = s[off + 12288];
        x = make_float4(a.x + b.x + c.x + d.x, a.y + b.y + c.y + d.y,
                        a.z + b.z + c.z + d.z, a.w + b.w + c.w + d.w);
    }
    ((uint2*)g_wh)[idx] = pack4h(x);
}

// ---------------- single-pass fp16 ldmatrix GEMM -----------------------------
// C(Mx128) = A @ W^T [+Res]. 128x128 tile, 8 warps (warp tile 32x64), 2 CTA/SM.
// VOUT: 0 = fp32 C (+Res), 1 = q into interleaved g_qv, 2 = v into g_qv.
#define PL 34816
#define SM_NEED2 (2 * PL)   // 69632

template <int VOUT>
__global__ __launch_bounds__(256, 2) void gemm3_k(
    const uint32_t* __restrict__ Ah, const uint32_t* __restrict__ Wh,
    const float* __restrict__ Res, float* __restrict__ C,
    uint32_t* __restrict__ Cv, int M)
{
    extern __shared__ char sm[];
    int tid = threadIdx.x, lane = tid & 31, wid = tid >> 5;
    int m0 = blockIdx.x * 128;

    // ---- stage A and W planes: LDG.128 -> STS.128 ----
    const uint4* A4 = (const uint4*)Ah;
    const uint4* W4 = (const uint4*)Wh;
    uint4 z = make_uint4(0, 0, 0, 0);
#pragma unroll
    for (int i = 0; i < 8; i++) {
        int c = tid + i * 256;
        int r = c >> 4, col = c & 15;
        bool v = (m0 + r) < M;
        uint4 av = v ? A4[(size_t)(m0 + r) * 16 + col] : z;
        char* d = sm + r * 272 + col * 16;
        *(uint4*)(d)      = av;
        *(uint4*)(d + PL) = W4[c];
    }
    __syncthreads();

    int wm = wid & 3, wn = wid >> 2;
    float acc[2][8][4];
#pragma unroll
    for (int mt = 0; mt < 2; mt++)
#pragma unroll
        for (int nt = 0; nt < 8; nt++)
#pragma unroll
            for (int i = 0; i < 4; i++) acc[mt][nt][i] = 0.f;

    uint32_t sb = smem_u32(sm);
    int lrow = lane & 15, lk = lane >> 4;
    uint32_t aB = sb + (wm * 32 + lrow) * 272 + lk * 16;
    uint32_t bB = sb + PL + (wn * 64 + lrow) * 272 + lk * 16;

#pragma unroll
    for (int k0 = 0; k0 < 8; k0++) {
        uint32_t a[2][4], b[4][4];
        LM4(a[0], aB + k0 * 32);
        LM4(a[1], aB + 16 * 272 + k0 * 32);
#pragma unroll
        for (int pr = 0; pr < 4; pr++)
            LM4(b[pr], bB + pr * 16 * 272 + k0 * 32);
#pragma unroll
        for (int mt = 0; mt < 2; mt++)
#pragma unroll
            for (int pr = 0; pr < 4; pr++) {
                mma16816h(acc[mt][pr * 2],
                          a[mt][0], a[mt][1], a[mt][2], a[mt][3],
                          b[pr][0], b[pr][2]);
                mma16816h(acc[mt][pr * 2 + 1],
                          a[mt][0], a[mt][1], a[mt][2], a[mt][3],
                          b[pr][1], b[pr][3]);
            }
    }

    // ---- epilogue ----
    int crow = m0 + wm * 32 + (lane >> 2);
    int ccol0 = wn * 64 + (lane & 3) * 2;
#pragma unroll
    for (int mt = 0; mt < 2; mt++)
#pragma unroll
        for (int half = 0; half < 2; half++) {
            int gm = crow + mt * 16 + half * 8;
            if (gm >= M) continue;
#pragma unroll
            for (int nt = 0; nt < 8; nt++) {
                float2 v2 = make_float2(acc[mt][nt][half * 2],
                                        acc[mt][nt][half * 2 + 1]);
                int col = ccol0 + nt * 8;
                if (VOUT) {
                    __half2 h = __float22half2_rn(v2);
                    int w = col >> 1;
                    int widx = 4 * (w >> 1) + (w & 1) + (VOUT == 2 ? 2 : 0);
                    Cv[(size_t)gm * 128 + widx] = *reinterpret_cast<uint32_t*>(&h);
                } else {
                    size_t gi = (size_t)gm * 128 + col;
                    if (Res) {
                        float2 r = *(const float2*)(Res + gi);
                        v2.x += r.x; v2.y += r.y;
                    }
                    *(float2*)(C + gi) = v2;
                }
            }
        }
}

// ---------------- CSR build + init ------------------------------------------
__global__ void zero_cnt_k() {
    int i = blockIdx.x * blockDim.x + threadIdx.x;
    if (i < NN) g_cnt[i] = 0;
}
__global__ void hist_k(const int* __restrict__ dst) {
    int e = blockIdx.x * blockDim.x + threadIdx.x;
    if (e < EE) atomicAdd(&g_cnt[dst[e]], 1);
}
__global__ void scan_k() {
    __shared__ int sums[1024];
    int tid = threadIdx.x;
    const int chunk = (NN + 1023) / 1024;
    int base = tid * chunk;
    int s = 0;
    for (int i = 0; i < chunk; i++) {
        int idx = base + i;
        if (idx < NN) s += g_cnt[idx];
    }
    sums[tid] = s;
    __syncthreads();
    for (int d = 1; d < 1024; d <<= 1) {
        int v = (tid >= d) ? sums[tid - d] : 0;
        __syncthreads();
        sums[tid] += v;
        __syncthreads();
    }
    int run = (tid == 0) ? 0 : sums[tid - 1];
    for (int i = 0; i < chunk; i++) {
        int idx = base + i;
        if (idx < NN) {
            g_off[idx] = run;
            g_cur[idx] = run;
            run += g_cnt[idx];
        }
    }
    if (tid == 0) g_off[NN] = sums[1023];
}
__global__ void scatter_k(const int* __restrict__ src, const int* __restrict__ dst) {
    int e = blockIdx.x * blockDim.x + threadIdx.x;
    if (e < EE) {
        int d = dst[e];
        int p = atomicAdd(&g_cur[d], 1);
        g_esrc[p] = src[e];
    }
}

// ---------------- fused score + softmax + aggregate (warp per dst) ----------
__device__ __forceinline__ float head_dot(uint4 qv, float4 k) {
    float2 q01 = __half22float2(*reinterpret_cast<__half2*>(&qv.x));
    float2 q23 = __half22float2(*reinterpret_cast<__half2*>(&qv.y));
    float p = q01.x * k.x + q01.y * k.y + q23.x * k.z + q23.y * k.w;
    p += __shfl_xor_sync(0xFFFFFFFFu, p, 4);
    p += __shfl_xor_sync(0xFFFFFFFFu, p, 2);
    p += __shfl_xor_sync(0xFFFFFFFFu, p, 1);
    return p;
}

__global__ void agg_k() {
    int n = (blockIdx.x * blockDim.x + threadIdx.x) >> 5;
    if (n >= NN) return;
    int lane = threadIdx.x & 31;

    int beg = g_off[n], end = g_off[n + 1];
    float4 kreg = ((const float4*)(g_k + (size_t)n * 128))[lane];
    const uint4* qv = (const uint4*)g_qv;

    const float scale = 0.17677669529663689f;  // 1/sqrt(32)
    float den = 0.f;
    float4 acc = make_float4(0.f, 0.f, 0.f, 0.f);

    int j = beg;
    for (; j + 1 < end; j += 2) {
        int s0 = g_esrc[j], s1 = g_esrc[j + 1];
        uint4 a0 = qv[(size_t)s0 * 32 + lane];
        uint4 a1 = qv[(size_t)s1 * 32 + lane];
        float p0 = head_dot(a0, kreg);
        float p1 = head_dot(a1, kreg);
        float e0 = __expf(p0 * scale);
        float e1 = __expf(p1 * scale);
        den += e0 + e1;
        float2 v01 = __half22float2(*reinterpret_cast<__half2*>(&a0.z));
        float2 v23 = __half22float2(*reinterpret_cast<__half2*>(&a0.w));
        float2 w01 = __half22float2(*reinterpret_cast<__half2*>(&a1.z));
        float2 w23 = __half22float2(*reinterpret_cast<__half2*>(&a1.w));
        acc.x += e0 * v01.x + e1 * w01.x;
        acc.y += e0 * v01.y + e1 * w01.y;
        acc.z += e0 * v23.x + e1 * w23.x;
        acc.w += e0 * v23.y + e1 * w23.y;
    }
    if (j < end) {
        int s0 = g_esrc[j];
        uint4 a0 = qv[(size_t)s0 * 32 + lane];
        float p0 = head_dot(a0, kreg);
        float e0 = __expf(p0 * scale);
        den += e0;
        float2 v01 = __half22float2(*reinterpret_cast<__half2*>(&a0.z));
        float2 v23 = __half22float2(*reinterpret_cast<__half2*>(&a0.w));
        acc.x += e0 * v01.x; acc.y += e0 * v01.y;
        acc.z += e0 * v23.x; acc.w += e0 * v23.y;
    }

    float inv = (end > beg) ? 1.f / den : 0.f;
    acc.x *= inv; acc.y *= inv; acc.z *= inv; acc.w *= inv;

    ((uint2*)g_fth)[(size_t)n * 32 + lane] = pack4h(acc);
}

// ---------------- launch ---------------------------------------------------
extern "C" void kernel_launch(void* const* d_in, const int* in_sizes, int n_in,
                              void* d_out, int out_size) {
    const float* feature = (const float*)d_in[0];
    const float* Wq      = (const float*)d_in[1];
    const float* Wk      = (const float*)d_in[2];
    const float* Wv      = (const float*)d_in[3];
    const float* Wscale  = (const float*)d_in[4];
    const int*   src     = (const int*)d_in[5];
    const int*   dst     = (const int*)d_in[6];
    float* out = (float*)d_out;

    static uint32_t *pfh = nullptr, *pqv, *pfth, *pwh;
    static float* pk;
    if (!pfh) {
        cudaGetSymbolAddress((void**)&pfh, g_fh);
        cudaGetSymbolAddress((void**)&pqv, g_qv);
        cudaGetSymbolAddress((void**)&pk,  g_k);
        cudaGetSymbolAddress((void**)&pfth, g_fth);
        cudaGetSymbolAddress((void**)&pwh, g_wh);
        cudaFuncSetAttribute(gemm3_k<0>,
                             cudaFuncAttributeMaxDynamicSharedMemorySize, SM_NEED2);
        cudaFuncSetAttribute(gemm3_k<1>,
                             cudaFuncAttributeMaxDynamicSharedMemorySize, SM_NEED2);
        cudaFuncSetAttribute(gemm3_k<2>,
                             cudaFuncAttributeMaxDynamicSharedMemorySize, SM_NEED2);
    }

    zero_cnt_k<<<(NN + 255) / 256, 256>>>();
    conv_w_k<<<(4 * 4096 + 255) / 256, 256>>>(Wq, Wk, Wv, Wscale);
    conv_feat_k<<<(NN * 32 + 255) / 256, 256>>>(feature);

    const int MT = (NN + 127) / 128;  // 391 tiles
    gemm3_k<1><<<MT, 256, SM_NEED2>>>(pfh, pwh + 0 * 8192, nullptr, nullptr, pqv, NN);
    gemm3_k<0><<<MT, 256, SM_NEED2>>>(pfh, pwh + 1 * 8192, nullptr, pk, nullptr, NN);
    gemm3_k<2><<<MT, 256, SM_NEED2>>>(pfh, pwh + 2 * 8192, nullptr, nullptr, pqv, NN);

    hist_k<<<(EE + 255) / 256, 256>>>(dst);
    scan_k<<<1, 1024>>>();
    scatter_k<<<(EE + 255) / 256, 256>>>(src, dst);

    agg_k<<<(NN * 32 + 255) / 256, 256>>>();

    gemm3_k<0><<<MT, 256, SM_NEED2>>>(pfth, pwh + 3 * 8192, feature, out, nullptr, NN);
}

// round 16
// speedup vs baseline: 1.0276x; 1.0276x over previous
#include <cuda_runtime.h>
#include <cuda_bf16.h>
#include <cuda_fp16.h>
#include <cstdint>

#define NN 50000
#define EE 800000
#define HH 4
#define INF_ 128

// ---------------- scratch ---------------------------------------------------
__device__ uint32_t g_fh [NN * 64];   // feature as fp16x2 (64 words/row)
__device__ uint32_t g_qv [NN * 128];  // interleaved q/v fp16x2: per lane l,
                                      // words 4l..4l+3 = {q2l, q2l+1, v2l, v2l+1}
__device__ float    g_k  [NN * 128];  // k fp32 (read once per node)
__device__ uint32_t g_fth[NN * 64];   // ft as fp16x2
__device__ uint32_t g_wh [4 * 8192];  // weights fp16x2 (q,k,v,weff)
__device__ int      g_cnt[NN];
__device__ int      g_off[NN + 1];
__device__ int      g_cur[NN];
__device__ int      g_esrc[EE];

// ---------------- helpers ----------------------------------------------------
__device__ __forceinline__ uint32_t smem_u32(const void* p) {
    uint32_t a;
    asm("{ .reg .u64 t; cvta.to.shared.u64 t, %1; cvt.u32.u64 %0, t; }" : "=r"(a) : "l"(p));
    return a;
}
__device__ __forceinline__ uint2 pack4h(float4 x) {
    __half2 h0 = __float22half2_rn(make_float2(x.x, x.y));
    __half2 h1 = __float22half2_rn(make_float2(x.z, x.w));
    uint2 r;
    r.x = *reinterpret_cast<uint32_t*>(&h0);
    r.y = *reinterpret_cast<uint32_t*>(&h1);
    return r;
}
__device__ __forceinline__ void mma16816h(float* d, uint32_t a0, uint32_t a1,
                                          uint32_t a2, uint32_t a3,
                                          uint32_t b0, uint32_t b1) {
    asm volatile(
        "mma.sync.aligned.m16n8k16.row.col.f32.f16.f16.f32 "
        "{%0,%1,%2,%3}, {%4,%5,%6,%7}, {%8,%9}, {%0,%1,%2,%3};"
        : "+f"(d[0]), "+f"(d[1]), "+f"(d[2]), "+f"(d[3])
        : "r"(a0), "r"(a1), "r"(a2), "r"(a3), "r"(b0), "r"(b1));
}
#define LM4(r, a) asm volatile( \
    "ldmatrix.sync.aligned.m8n8.x4.shared.b16 {%0,%1,%2,%3}, [%4];" \
    : "=r"((r)[0]), "=r"((r)[1]), "=r"((r)[2]), "=r"((r)[3]) : "r"(a))

// ---------------- conversion kernels ----------------------------------------
__global__ void conv_feat_k(const float* __restrict__ F) {
    int idx = blockIdx.x * blockDim.x + threadIdx.x;
    if (idx < NN * 32)
        ((uint2*)g_fh)[idx] = pack4h(((const float4*)F)[idx]);
}
__global__ void conv_w_k(const float* __restrict__ Wq, const float* __restrict__ Wk,
                         const float* __restrict__ Wv, const float* __restrict__ Ws) {
    int idx = blockIdx.x * blockDim.x + threadIdx.x;
    if (idx >= 4 * 4096) return;
    int w = idx >> 12, off = idx & 4095;
    float4 x;
    if (w == 0)      x = ((const float4*)Wq)[off];
    else if (w == 1) x = ((const float4*)Wk)[off];
    else if (w == 2) x = ((const float4*)Wv)[off];
    else {
        const float4* s = (const float4*)Ws;
        float4 a = s[off], b = s[off + 4096], c = s[off + 8192], d = s[off + 12288];
        x = make_float4(a.x + b.x + c.x + d.x, a.y + b.y + c.y + d.y,
                        a.z + b.z + c.z + d.z, a.w + b.w + c.w + d.w);
    }
    ((uint2*)g_wh)[idx] = pack4h(x);
}

// ---------------- single-pass fp16 ldmatrix GEMM -----------------------------
// C(Mx128) = A @ W^T [+Res]. 128x128 tile, 8 warps (warp tile 32x64), 2 CTA/SM.
// VOUT: 0 = fp32 C (+Res), 1 = q into interleaved g_qv, 2 = v into g_qv.
#define PL 34816
#define SM_NEED2 (2 * PL)   // 69632

template <int VOUT>
__global__ __launch_bounds__(256, 2) void gemm3_k(
    const uint32_t* __restrict__ Ah, const uint32_t* __restrict__ Wh,
    const float* __restrict__ Res, float* __restrict__ C,
    uint32_t* __restrict__ Cv, int M)
{
    extern __shared__ char sm[];
    int tid = threadIdx.x, lane = tid & 31, wid = tid >> 5;
    int m0 = blockIdx.x * 128;

    // ---- stage A and W planes: LDG.128 -> STS.128 ----
    const uint4* A4 = (const uint4*)Ah;
    const uint4* W4 = (const uint4*)Wh;
    uint4 z = make_uint4(0, 0, 0, 0);
#pragma unroll
    for (int i = 0; i < 8; i++) {
        int c = tid + i * 256;
        int r = c >> 4, col = c & 15;
        bool v = (m0 + r) < M;
        uint4 av = v ? A4[(size_t)(m0 + r) * 16 + col] : z;
        char* d = sm + r * 272 + col * 16;
        *(uint4*)(d)      = av;
        *(uint4*)(d + PL) = W4[c];
    }
    __syncthreads();

    int wm = wid & 3, wn = wid >> 2;
    float acc[2][8][4];
#pragma unroll
    for (int mt = 0; mt < 2; mt++)
#pragma unroll
        for (int nt = 0; nt < 8; nt++)
#pragma unroll
            for (int i = 0; i < 4; i++) acc[mt][nt][i] = 0.f;

    uint32_t sb = smem_u32(sm);
    int lrow = lane & 15, lk = lane >> 4;
    uint32_t aB = sb + (wm * 32 + lrow) * 272 + lk * 16;
    uint32_t bB = sb + PL + (wn * 64 + lrow) * 272 + lk * 16;

#pragma unroll
    for (int k0 = 0; k0 < 8; k0++) {
        uint32_t a[2][4], b[4][4];
        LM4(a[0], aB + k0 * 32);
        LM4(a[1], aB + 16 * 272 + k0 * 32);
#pragma unroll
        for (int pr = 0; pr < 4; pr++)
            LM4(b[pr], bB + pr * 16 * 272 + k0 * 32);
#pragma unroll
        for (int mt = 0; mt < 2; mt++)
#pragma unroll
            for (int pr = 0; pr < 4; pr++) {
                mma16816h(acc[mt][pr * 2],
                          a[mt][0], a[mt][1], a[mt][2], a[mt][3],
                          b[pr][0], b[pr][2]);
                mma16816h(acc[mt][pr * 2 + 1],
                          a[mt][0], a[mt][1], a[mt][2], a[mt][3],
                          b[pr][1], b[pr][3]);
            }
    }

    // ---- epilogue ----
    int crow = m0 + wm * 32 + (lane >> 2);
    int ccol0 = wn * 64 + (lane & 3) * 2;
#pragma unroll
    for (int mt = 0; mt < 2; mt++)
#pragma unroll
        for (int half = 0; half < 2; half++) {
            int gm = crow + mt * 16 + half * 8;
            if (gm >= M) continue;
#pragma unroll
            for (int nt = 0; nt < 8; nt++) {
                float2 v2 = make_float2(acc[mt][nt][half * 2],
                                        acc[mt][nt][half * 2 + 1]);
                int col = ccol0 + nt * 8;
                if (VOUT) {
                    __half2 h = __float22half2_rn(v2);
                    int w = col >> 1;
                    int widx = 4 * (w >> 1) + (w & 1) + (VOUT == 2 ? 2 : 0);
                    Cv[(size_t)gm * 128 + widx] = *reinterpret_cast<uint32_t*>(&h);
                } else {
                    size_t gi = (size_t)gm * 128 + col;
                    if (Res) {
                        float2 r = *(const float2*)(Res + gi);
                        v2.x += r.x; v2.y += r.y;
                    }
                    *(float2*)(C + gi) = v2;
                }
            }
        }
}

// ---------------- CSR build + init ------------------------------------------
__global__ void zero_cnt_k() {
    int i = blockIdx.x * blockDim.x + threadIdx.x;
    if (i < NN) g_cnt[i] = 0;
}
__global__ void hist_k(const int* __restrict__ dst) {
    int e = blockIdx.x * blockDim.x + threadIdx.x;
    if (e < EE) atomicAdd(&g_cnt[dst[e]], 1);
}
__global__ void scan_k() {
    __shared__ int sums[1024];
    int tid = threadIdx.x;
    const int chunk = (NN + 1023) / 1024;
    int base = tid * chunk;
    int s = 0;
    for (int i = 0; i < chunk; i++) {
        int idx = base + i;
        if (idx < NN) s += g_cnt[idx];
    }
    sums[tid] = s;
    __syncthreads();
    for (int d = 1; d < 1024; d <<= 1) {
        int v = (tid >= d) ? sums[tid - d] : 0;
        __syncthreads();
        sums[tid] += v;
        __syncthreads();
    }
    int run = (tid == 0) ? 0 : sums[tid - 1];
    for (int i = 0; i < chunk; i++) {
        int idx = base + i;
        if (idx < NN) {
            g_off[idx] = run;
            g_cur[idx] = run;
            run += g_cnt[idx];
        }
    }
    if (tid == 0) g_off[NN] = sums[1023];
}
__global__ void scatter_k(const int* __restrict__ src, const int* __restrict__ dst) {
    int e = blockIdx.x * blockDim.x + threadIdx.x;
    if (e < EE) {
        int d = dst[e];
        int p = atomicAdd(&g_cur[d], 1);
        g_esrc[p] = src[e];
    }
}

// ---------------- fused score + softmax + aggregate (warp per dst) ----------
// Software-pipelined at x4: batch index loads, issue 4 independent gathers,
// then 4 interleaved shfl-reduction chains. MLP=4 on the gather path.
__device__ __forceinline__ float head_dot(uint4 qv, float4 k) {
    float2 q01 = __half22float2(*reinterpret_cast<__half2*>(&qv.x));
    float2 q23 = __half22float2(*reinterpret_cast<__half2*>(&qv.y));
    float p = q01.x * k.x + q01.y * k.y + q23.x * k.z + q23.y * k.w;
    p += __shfl_xor_sync(0xFFFFFFFFu, p, 4);
    p += __shfl_xor_sync(0xFFFFFFFFu, p, 2);
    p += __shfl_xor_sync(0xFFFFFFFFu, p, 1);
    return p;
}
__device__ __forceinline__ void acc_edge(float4& acc, float& den, uint4 a,
                                         float e) {
    den += e;
    float2 v01 = __half22float2(*reinterpret_cast<__half2*>(&a.z));
    float2 v23 = __half22float2(*reinterpret_cast<__half2*>(&a.w));
    acc.x += e * v01.x; acc.y += e * v01.y;
    acc.z += e * v23.x; acc.w += e * v23.y;
}

__global__ void agg_k() {
    int n = (blockIdx.x * blockDim.x + threadIdx.x) >> 5;
    if (n >= NN) return;
    int lane = threadIdx.x & 31;

    int beg = g_off[n], end = g_off[n + 1];
    float4 kreg = ((const float4*)(g_k + (size_t)n * 128))[lane];
    const uint4* qv = (const uint4*)g_qv;

    const float scale = 0.17677669529663689f;  // 1/sqrt(32)
    float den = 0.f;
    float4 acc = make_float4(0.f, 0.f, 0.f, 0.f);

    int j = beg;
    for (; j + 3 < end; j += 4) {
        // batch indices first (sequential, cache-friendly)
        int s0 = g_esrc[j],     s1 = g_esrc[j + 1];
        int s2 = g_esrc[j + 2], s3 = g_esrc[j + 3];
        // issue 4 independent gathers (MLP=4)
        uint4 a0 = qv[(size_t)s0 * 32 + lane];
        uint4 a1 = qv[(size_t)s1 * 32 + lane];
        uint4 a2 = qv[(size_t)s2 * 32 + lane];
        uint4 a3 = qv[(size_t)s3 * 32 + lane];
        // 4 interleaved shfl-reduction chains
        float p0 = head_dot(a0, kreg);
        float p1 = head_dot(a1, kreg);
        float p2 = head_dot(a2, kreg);
        float p3 = head_dot(a3, kreg);
        float e0 = __expf(p0 * scale), e1 = __expf(p1 * scale);
        float e2 = __expf(p2 * scale), e3 = __expf(p3 * scale);
        acc_edge(acc, den, a0, e0);
        acc_edge(acc, den, a1, e1);
        acc_edge(acc, den, a2, e2);
        acc_edge(acc, den, a3, e3);
    }
    for (; j < end; j++) {
        int s0 = g_esrc[j];
        uint4 a0 = qv[(size_t)s0 * 32 + lane];
        float p0 = head_dot(a0, kreg);
        float e0 = __expf(p0 * scale);
        acc_edge(acc, den, a0, e0);
    }

    float inv = (end > beg) ? 1.f / den : 0.f;
    acc.x *= inv; acc.y *= inv; acc.z *= inv; acc.w *= inv;

    ((uint2*)g_fth)[(size_t)n * 32 + lane] = pack4h(acc);
}

// ---------------- launch ---------------------------------------------------
extern "C" void kernel_launch(void* const* d_in, const int* in_sizes, int n_in,
                              void* d_out, int out_size) {
    const float* feature = (const float*)d_in[0];
    const float* Wq      = (const float*)d_in[1];
    const float* Wk      = (const float*)d_in[2];
    const float* Wv      = (const float*)d_in[3];
    const float* Wscale  = (const float*)d_in[4];
    const int*   src     = (const int*)d_in[5];
    const int*   dst     = (const int*)d_in[6];
    float* out = (float*)d_out;

    static uint32_t *pfh = nullptr, *pqv, *pfth, *pwh;
    static float* pk;
    if (!pfh) {
        cudaGetSymbolAddress((void**)&pfh, g_fh);
        cudaGetSymbolAddress((void**)&pqv, g_qv);
        cudaGetSymbolAddress((void**)&pk,  g_k);
        cudaGetSymbolAddress((void**)&pfth, g_fth);
        cudaGetSymbolAddress((void**)&pwh, g_wh);
        cudaFuncSetAttribute(gemm3_k<0>,
                             cudaFuncAttributeMaxDynamicSharedMemorySize, SM_NEED2);
        cudaFuncSetAttribute(gemm3_k<1>,
                             cudaFuncAttributeMaxDynamicSharedMemorySize, SM_NEED2);
        cudaFuncSetAttribute(gemm3_k<2>,
                             cudaFuncAttributeMaxDynamicSharedMemorySize, SM_NEED2);
    }

    zero_cnt_k<<<(NN + 255) / 256, 256>>>();
    conv_w_k<<<(4 * 4096 + 255) / 256, 256>>>(Wq, Wk, Wv, Wscale);
    conv_feat_k<<<(NN * 32 + 255) / 256, 256>>>(feature);

    const int MT = (NN + 127) / 128;  // 391 tiles
    gemm3_k<1><<<MT, 256, SM_NEED2>>>(pfh, pwh + 0 * 8192, nullptr, nullptr, pqv, NN);
    gemm3_k<0><<<MT, 256, SM_NEED2>>>(pfh, pwh + 1 * 8192, nullptr, pk, nullptr, NN);
    gemm3_k<2><<<MT, 256, SM_NEED2>>>(pfh, pwh + 2 * 8192, nullptr, nullptr, pqv, NN);

    hist_k<<<(EE + 255) / 256, 256>>>(dst);
    scan_k<<<1, 1024>>>();
    scatter_k<<<(EE + 255) / 256, 256>>>(src, dst);

    agg_k<<<(NN * 32 + 255) / 256, 256>>>();

    gemm3_k<0><<<MT, 256, SM_NEED2>>>(pfth, pwh + 3 * 8192, feature, out, nullptr, NN);
}

// round 17
// speedup vs baseline: 1.7344x; 1.6877x over previous
#include <cuda_runtime.h>
#include <cuda_bf16.h>
#include <cuda_fp16.h>
#include <cstdint>

#define NN 50000
#define EE 800000
#define HH 4
#define INF_ 128

// ---------------- scratch ---------------------------------------------------
__device__ uint32_t g_fh [NN * 64];   // feature as fp16x2 (64 words/row)
__device__ uint32_t g_qv [NN * 128];  // interleaved q/v fp16x2: per lane l,
                                      // words 4l..4l+3 = {q2l, q2l+1, v2l, v2l+1}
__device__ float    g_k  [NN * 128];  // k fp32 (read once per node)
__device__ uint32_t g_fth[NN * 64];   // ft as fp16x2
__device__ uint32_t g_wh [4 * 8192];  // weights fp16x2 (q,k,v,weff)
__device__ int      g_cnt[NN];
__device__ int      g_off[NN + 1];
__device__ int      g_cur[NN];
__device__ int      g_esrc[EE];
#define SNB 49                        // scan blocks (49*1024 >= 50000)
__device__ int      g_bsum[SNB];

// ---------------- helpers ----------------------------------------------------
__device__ __forceinline__ uint32_t smem_u32(const void* p) {
    uint32_t a;
    asm("{ .reg .u64 t; cvta.to.shared.u64 t, %1; cvt.u32.u64 %0, t; }" : "=r"(a) : "l"(p));
    return a;
}
__device__ __forceinline__ uint2 pack4h(float4 x) {
    __half2 h0 = __float22half2_rn(make_float2(x.x, x.y));
    __half2 h1 = __float22half2_rn(make_float2(x.z, x.w));
    uint2 r;
    r.x = *reinterpret_cast<uint32_t*>(&h0);
    r.y = *reinterpret_cast<uint32_t*>(&h1);
    return r;
}
__device__ __forceinline__ void mma16816h(float* d, uint32_t a0, uint32_t a1,
                                          uint32_t a2, uint32_t a3,
                                          uint32_t b0, uint32_t b1) {
    asm volatile(
        "mma.sync.aligned.m16n8k16.row.col.f32.f16.f16.f32 "
        "{%0,%1,%2,%3}, {%4,%5,%6,%7}, {%8,%9}, {%0,%1,%2,%3};"
        : "+f"(d[0]), "+f"(d[1]), "+f"(d[2]), "+f"(d[3])
        : "r"(a0), "r"(a1), "r"(a2), "r"(a3), "r"(b0), "r"(b1));
}
#define LM4(r, a) asm volatile( \
    "ldmatrix.sync.aligned.m8n8.x4.shared.b16 {%0,%1,%2,%3}, [%4];" \
    : "=r"((r)[0]), "=r"((r)[1]), "=r"((r)[2]), "=r"((r)[3]) : "r"(a))

// ---------------- conversion kernels ----------------------------------------
__global__ void conv_feat_k(const float* __restrict__ F) {
    int idx = blockIdx.x * blockDim.x + threadIdx.x;
    if (idx < NN * 32)
        ((uint2*)g_fh)[idx] = pack4h(((const float4*)F)[idx]);
}
__global__ void conv_w_k(const float* __restrict__ Wq, const float* __restrict__ Wk,
                         const float* __restrict__ Wv, const float* __restrict__ Ws) {
    int idx = blockIdx.x * blockDim.x + threadIdx.x;
    if (idx >= 4 * 4096) return;
    int w = idx >> 12, off = idx & 4095;
    float4 x;
    if (w == 0)      x = ((const float4*)Wq)[off];
    else if (w == 1) x = ((const float4*)Wk)[off];
    else if (w == 2) x = ((const float4*)Wv)[off];
    else {
        const float4* s = (const float4*)Ws;
        float4 a = s[off], b = s[off + 4096], c = s[off + 8192], d = s[off + 12288];
        x = make_float4(a.x + b.x + c.x + d.x, a.y + b.y + c.y + d.y,
                        a.z + b.z + c.z + d.z, a.w + b.w + c.w + d.w);
    }
    ((uint2*)g_wh)[idx] = pack4h(x);
}

// ---------------- GEMM common pieces ----------------------------------------
#define PL 34816
#define SM_NEED2 (2 * PL)   // single-weight GEMM
#define SM_NEED3 (3 * PL)   // fused QKV (A + 2 W buffers)

// ---- fused QKV GEMM: stage A once, double-buffer 3 weights ----
__global__ __launch_bounds__(256, 2) void qkv_gemm_k(
    const uint32_t* __restrict__ Ah, const uint32_t* __restrict__ Wh,
    float* __restrict__ Ck, uint32_t* __restrict__ Cqv, int M)
{
    extern __shared__ char sm[];
    int tid = threadIdx.x, lane = tid & 31, wid = tid >> 5;
    int m0 = blockIdx.x * 128;

    const uint4* A4 = (const uint4*)Ah;
    const uint4* W4 = (const uint4*)Wh;
    uint4 z = make_uint4(0, 0, 0, 0);
#pragma unroll
    for (int i = 0; i < 8; i++) {
        int c = tid + i * 256;
        int r = c >> 4, col = c & 15;
        bool v = (m0 + r) < M;
        uint4 av = v ? A4[(size_t)(m0 + r) * 16 + col] : z;
        char* d = sm + r * 272 + col * 16;
        *(uint4*)(d)      = av;
        *(uint4*)(d + PL) = W4[c];          // W0 -> buf0
    }
    __syncthreads();

    int wm = wid & 3, wn = wid >> 2;
    uint32_t sb = smem_u32(sm);
    int lrow = lane & 15, lk = lane >> 4;
    uint32_t aB = sb + (wm * 32 + lrow) * 272 + lk * 16;

    int crow = m0 + wm * 32 + (lane >> 2);
    int ccol0 = wn * 64 + (lane & 3) * 2;

    for (int w = 0; w < 3; w++) {
        // prefetch next weight into the other buffer (no race: different plane)
        if (w < 2) {
            const uint4* Wn = W4 + (w + 1) * 2048;
            char* db = sm + PL + ((w + 1) & 1) * PL;
#pragma unroll
            for (int i = 0; i < 8; i++) {
                int c = tid + i * 256;
                *(uint4*)(db + (c >> 4) * 272 + (c & 15) * 16) = Wn[c];
            }
        }

        float acc[2][8][4];
#pragma unroll
        for (int mt = 0; mt < 2; mt++)
#pragma unroll
            for (int nt = 0; nt < 8; nt++)
#pragma unroll
                for (int i = 0; i < 4; i++) acc[mt][nt][i] = 0.f;

        uint32_t bB = sb + PL + (w & 1) * PL + (wn * 64 + lrow) * 272 + lk * 16;
#pragma unroll
        for (int k0 = 0; k0 < 8; k0++) {
            uint32_t a[2][4], b[4][4];
            LM4(a[0], aB + k0 * 32);
            LM4(a[1], aB + 16 * 272 + k0 * 32);
#pragma unroll
            for (int pr = 0; pr < 4; pr++)
                LM4(b[pr], bB + pr * 16 * 272 + k0 * 32);
#pragma unroll
            for (int mt = 0; mt < 2; mt++)
#pragma unroll
                for (int pr = 0; pr < 4; pr++) {
                    mma16816h(acc[mt][pr * 2],
                              a[mt][0], a[mt][1], a[mt][2], a[mt][3],
                              b[pr][0], b[pr][2]);
                    mma16816h(acc[mt][pr * 2 + 1],
                              a[mt][0], a[mt][1], a[mt][2], a[mt][3],
                              b[pr][1], b[pr][3]);
                }
        }

        // epilogue: w0 -> q (interleave), w1 -> k fp32, w2 -> v (interleave)
#pragma unroll
        for (int mt = 0; mt < 2; mt++)
#pragma unroll
            for (int half = 0; half < 2; half++) {
                int gm = crow + mt * 16 + half * 8;
                if (gm >= M) continue;
#pragma unroll
                for (int nt = 0; nt < 8; nt++) {
                    float2 v2 = make_float2(acc[mt][nt][half * 2],
                                            acc[mt][nt][half * 2 + 1]);
                    int col = ccol0 + nt * 8;
                    if (w == 1) {
                        *(float2*)(Ck + (size_t)gm * 128 + col) = v2;
                    } else {
                        __half2 h = __float22half2_rn(v2);
                        int ww = col >> 1;
                        int widx = 4 * (ww >> 1) + (ww & 1) + (w == 2 ? 2 : 0);
                        Cqv[(size_t)gm * 128 + widx] = *reinterpret_cast<uint32_t*>(&h);
                    }
                }
            }
        __syncthreads();
    }
}

// ---- single-weight GEMM (final layer): fp32 out + residual ----
__global__ __launch_bounds__(256, 2) void gemm3_k(
    const uint32_t* __restrict__ Ah, const uint32_t* __restrict__ Wh,
    const float* __restrict__ Res, float* __restrict__ C, int M)
{
    extern __shared__ char sm[];
    int tid = threadIdx.x, lane = tid & 31, wid = tid >> 5;
    int m0 = blockIdx.x * 128;

    const uint4* A4 = (const uint4*)Ah;
    const uint4* W4 = (const uint4*)Wh;
    uint4 z = make_uint4(0, 0, 0, 0);
#pragma unroll
    for (int i = 0; i < 8; i++) {
        int c = tid + i * 256;
        int r = c >> 4, col = c & 15;
        bool v = (m0 + r) < M;
        uint4 av = v ? A4[(size_t)(m0 + r) * 16 + col] : z;
        char* d = sm + r * 272 + col * 16;
        *(uint4*)(d)      = av;
        *(uint4*)(d + PL) = W4[c];
    }
    __syncthreads();

    int wm = wid & 3, wn = wid >> 2;
    float acc[2][8][4];
#pragma unroll
    for (int mt = 0; mt < 2; mt++)
#pragma unroll
        for (int nt = 0; nt < 8; nt++)
#pragma unroll
            for (int i = 0; i < 4; i++) acc[mt][nt][i] = 0.f;

    uint32_t sb = smem_u32(sm);
    int lrow = lane & 15, lk = lane >> 4;
    uint32_t aB = sb + (wm * 32 + lrow) * 272 + lk * 16;
    uint32_t bB = sb + PL + (wn * 64 + lrow) * 272 + lk * 16;

#pragma unroll
    for (int k0 = 0; k0 < 8; k0++) {
        uint32_t a[2][4], b[4][4];
        LM4(a[0], aB + k0 * 32);
        LM4(a[1], aB + 16 * 272 + k0 * 32);
#pragma unroll
        for (int pr = 0; pr < 4; pr++)
            LM4(b[pr], bB + pr * 16 * 272 + k0 * 32);
#pragma unroll
        for (int mt = 0; mt < 2; mt++)
#pragma unroll
            for (int pr = 0; pr < 4; pr++) {
                mma16816h(acc[mt][pr * 2],
                          a[mt][0], a[mt][1], a[mt][2], a[mt][3],
                          b[pr][0], b[pr][2]);
                mma16816h(acc[mt][pr * 2 + 1],
                          a[mt][0], a[mt][1], a[mt][2], a[mt][3],
                          b[pr][1], b[pr][3]);
            }
    }

    int crow = m0 + wm * 32 + (lane >> 2);
    int ccol0 = wn * 64 + (lane & 3) * 2;
#pragma unroll
    for (int mt = 0; mt < 2; mt++)
#pragma unroll
        for (int half = 0; half < 2; half++) {
            int gm = crow + mt * 16 + half * 8;
            if (gm >= M) continue;
#pragma unroll
            for (int nt = 0; nt < 8; nt++) {
                float2 v2 = make_float2(acc[mt][nt][half * 2],
                                        acc[mt][nt][half * 2 + 1]);
                size_t gi = (size_t)gm * 128 + ccol0 + nt * 8;
                float2 r = *(const float2*)(Res + gi);
                v2.x += r.x; v2.y += r.y;
                *(float2*)(C + gi) = v2;
            }
        }
}

// ---------------- CSR build (parallel 3-phase scan) --------------------------
__global__ void zero_cnt_k() {
    int i = blockIdx.x * blockDim.x + threadIdx.x;
    if (i < NN) g_cnt[i] = 0;
}
__global__ void hist_k(const int* __restrict__ dst) {
    int e = blockIdx.x * blockDim.x + threadIdx.x;
    if (e < EE) atomicAdd(&g_cnt[dst[e]], 1);
}
__global__ void scanA_k() {   // 49 blocks x 1024: per-block totals
    __shared__ int sh[1024];
    int t = threadIdx.x, idx = blockIdx.x * 1024 + t;
    sh[t] = (idx < NN) ? g_cnt[idx] : 0;
    __syncthreads();
#pragma unroll
    for (int d = 512; d > 0; d >>= 1) {
        if (t < d) sh[t] += sh[t + d];
        __syncthreads();
    }
    if (t == 0) g_bsum[blockIdx.x] = sh[0];
}
__global__ void scanB_k() {   // 1 block x 64: exclusive scan of 49 totals
    __shared__ int sh[64];
    int t = threadIdx.x;
    int orig = (t < SNB) ? g_bsum[t] : 0;
    sh[t] = orig;
    __syncthreads();
#pragma unroll
    for (int d = 1; d < 64; d <<= 1) {
        int v = (t >= d) ? sh[t - d] : 0;
        __syncthreads();
        sh[t] += v;
        __syncthreads();
    }
    if (t < SNB) g_bsum[t] = sh[t] - orig;
    if (t == 0) g_off[NN] = EE;
}
__global__ void scanC_k() {   // 49 blocks x 1024: intra-block scan + base
    __shared__ int sh[1024];
    int t = threadIdx.x, idx = blockIdx.x * 1024 + t;
    int orig = (idx < NN) ? g_cnt[idx] : 0;
    sh[t] = orig;
    __syncthreads();
#pragma unroll
    for (int d = 1; d < 1024; d <<= 1) {
        int v = (t >= d) ? sh[t - d] : 0;
        __syncthreads();
        sh[t] += v;
        __syncthreads();
    }
    if (idx < NN) {
        int off = g_bsum[blockIdx.x] + sh[t] - orig;
        g_off[idx] = off;
        g_cur[idx] = off;
    }
}
__global__ void scatter_k(const int* __restrict__ src, const int* __restrict__ dst) {
    int e = blockIdx.x * blockDim.x + threadIdx.x;
    if (e < EE) {
        int d = dst[e];
        int p = atomicAdd(&g_cur[d], 1);
        g_esrc[p] = src[e];
    }
}

// ---------------- fused score + softmax + aggregate (warp per dst) ----------
__device__ __forceinline__ float head_dot(uint4 qv, float4 k) {
    float2 q01 = __half22float2(*reinterpret_cast<__half2*>(&qv.x));
    float2 q23 = __half22float2(*reinterpret_cast<__half2*>(&qv.y));
    float p = q01.x * k.x + q01.y * k.y + q23.x * k.z + q23.y * k.w;
    p += __shfl_xor_sync(0xFFFFFFFFu, p, 4);
    p += __shfl_xor_sync(0xFFFFFFFFu, p, 2);
    p += __shfl_xor_sync(0xFFFFFFFFu, p, 1);
    return p;
}
__device__ __forceinline__ void acc_edge(float4& acc, float& den, uint4 a,
                                         float e) {
    den += e;
    float2 v01 = __half22float2(*reinterpret_cast<__half2*>(&a.z));
    float2 v23 = __half22float2(*reinterpret_cast<__half2*>(&a.w));
    acc.x += e * v01.x; acc.y += e * v01.y;
    acc.z += e * v23.x; acc.w += e * v23.y;
}

__global__ void agg_k() {
    int n = (blockIdx.x * blockDim.x + threadIdx.x) >> 5;
    if (n >= NN) return;
    int lane = threadIdx.x & 31;

    int beg = g_off[n], end = g_off[n + 1];
    float4 kreg = ((const float4*)(g_k + (size_t)n * 128))[lane];
    const uint4* qv = (const uint4*)g_qv;

    const float scale = 0.17677669529663689f;  // 1/sqrt(32)
    float den = 0.f;
    float4 acc = make_float4(0.f, 0.f, 0.f, 0.f);

    int j = beg;
    for (; j + 3 < end; j += 4) {
        int s0 = g_esrc[j],     s1 = g_esrc[j + 1];
        int s2 = g_esrc[j + 2], s3 = g_esrc[j + 3];
        uint4 a0 = qv[(size_t)s0 * 32 + lane];
        uint4 a1 = qv[(size_t)s1 * 32 + lane];
        uint4 a2 = qv[(size_t)s2 * 32 + lane];
        uint4 a3 = qv[(size_t)s3 * 32 + lane];
        float p0 = head_dot(a0, kreg);
        float p1 = head_dot(a1, kreg);
        float p2 = head_dot(a2, kreg);
        float p3 = head_dot(a3, kreg);
        float e0 = __expf(p0 * scale), e1 = __expf(p1 * scale);
        float e2 = __expf(p2 * scale), e3 = __expf(p3 * scale);
        acc_edge(acc, den, a0, e0);
        acc_edge(acc, den, a1, e1);
        acc_edge(acc, den, a2, e2);
        acc_edge(acc, den, a3, e3);
    }
    for (; j < end; j++) {
        int s0 = g_esrc[j];
        uint4 a0 = qv[(size_t)s0 * 32 + lane];
        float p0 = head_dot(a0, kreg);
        float e0 = __expf(p0 * scale);
        acc_edge(acc, den, a0, e0);
    }

    float inv = (end > beg) ? 1.f / den : 0.f;
    acc.x *= inv; acc.y *= inv; acc.z *= inv; acc.w *= inv;

    ((uint2*)g_fth)[(size_t)n * 32 + lane] = pack4h(acc);
}

// ---------------- launch ---------------------------------------------------
extern "C" void kernel_launch(void* const* d_in, const int* in_sizes, int n_in,
                              void* d_out, int out_size) {
    const float* feature = (const float*)d_in[0];
    const float* Wq      = (const float*)d_in[1];
    const float* Wk      = (const float*)d_in[2];
    const float* Wv      = (const float*)d_in[3];
    const float* Wscale  = (const float*)d_in[4];
    const int*   src     = (const int*)d_in[5];
    const int*   dst     = (const int*)d_in[6];
    float* out = (float*)d_out;

    static uint32_t *pfh = nullptr, *pqv, *pfth, *pwh;
    static float* pk;
    if (!pfh) {
        cudaGetSymbolAddress((void**)&pfh, g_fh);
        cudaGetSymbolAddress((void**)&pqv, g_qv);
        cudaGetSymbolAddress((void**)&pk,  g_k);
        cudaGetSymbolAddress((void**)&pfth, g_fth);
        cudaGetSymbolAddress((void**)&pwh, g_wh);
        cudaFuncSetAttribute(qkv_gemm_k,
                             cudaFuncAttributeMaxDynamicSharedMemorySize, SM_NEED3);
        cudaFuncSetAttribute(gemm3_k,
                             cudaFuncAttributeMaxDynamicSharedMemorySize, SM_NEED2);
    }

    zero_cnt_k<<<(NN + 255) / 256, 256>>>();
    conv_w_k<<<(4 * 4096 + 255) / 256, 256>>>(Wq, Wk, Wv, Wscale);
    conv_feat_k<<<(NN * 32 + 255) / 256, 256>>>(feature);

    const int MT = (NN + 127) / 128;  // 391 tiles
    qkv_gemm_k<<<MT, 256, SM_NEED3>>>(pfh, pwh, pk, pqv, NN);

    hist_k<<<(EE + 255) / 256, 256>>>(dst);
    scanA_k<<<SNB, 1024>>>();
    scanB_k<<<1, 64>>>();
    scanC_k<<<SNB, 1024>>>();
    scatter_k<<<(EE + 255) / 256, 256>>>(src, dst);

    agg_k<<<(NN * 32 + 255) / 256, 256>>>();

    gemm3_k<<<MT, 256, SM_NEED2>>>(pfth, pwh + 3 * 8192, feature, out, NN);
}